// round 16
// baseline (speedup 1.0000x reference)
#include <cuda_runtime.h>
#include <math.h>

#define NT 384
#define IT 4
typedef unsigned long long u64;

// ---------------- shared memory layout (floats), 4 items per CTA ----------------
constexpr int FS  = 1536;  // f per-item stride
constexpr int RPS = 1176;  // rp per-item stride (max 6*196)
constexpr int NCH = 12;    // hid channels per chunk (4 chunks of 12)
constexpr int HS  = NCH * 196;  // hid per-item stride = 2352
constexpr int OFF_F    = 0;      // f:   [4][1536] = 6144
constexpr int OFF_RP   = 6144;   // rp:  [4][1176] = 4704 (reused as zbuf)
constexpr int OFF_HID  = 10848;  // hid: [4][12*196] = 9408
constexpr int OFF_W1   = 20256;  // conv1 weights plain [48][6][9] = 2592 (shared)
constexpr int OFF_W2P  = 22848;  // conv2 dup f32x2 chunk [6][145] = 1740 (shared)
constexpr int OFF_B1   = 24588;  // 48
constexpr int OFF_B2   = 24636;  // 8
constexpr int SMEM_FLOATS = 24644;
constexpr int SMEM_BYTES  = SMEM_FLOATS * 4;   // 98,576 B -> 2 blocks/SM

constexpr int S2K = 145;   // conv2 per-k stride in f32x2 (12*12 + 1 pad)

// ---------------- f32x2 packed helpers ----------------
__device__ __forceinline__ u64 pack2(float lo, float hi) {
    u64 r; asm("mov.b64 %0, {%1, %2};" : "=l"(r) : "f"(lo), "f"(hi)); return r;
}
__device__ __forceinline__ void unpack2(u64 v, float& lo, float& hi) {
    asm("mov.b64 {%0, %1}, %2;" : "=f"(lo), "=f"(hi) : "l"(v));
}
__device__ __forceinline__ void fma2(u64& d, u64 a, u64 b) {
    asm("fma.rn.f32x2 %0, %1, %2, %0;" : "+l"(d) : "l"(a), "l"(b));
}
__device__ __forceinline__ u64 lds2(const float* p) {
    return *reinterpret_cast<const u64*>(p);
}

// ---------------- XLA-exact tanh (verified bit-exact) ----------------
__device__ __forceinline__ float xla_tanh(float x) {
    if (fabsf(x) < 0.0004f) return x;
    float xc = fminf(fmaxf(x, -7.90531110763549805f), 7.90531110763549805f);
    float x2 = __fmul_rn(xc, xc);
    float p = fmaf(x2, -2.76076847742355e-16f, 2.00018790482477e-13f);
    p = fmaf(x2, p, -8.60467152213735e-11f);
    p = fmaf(x2, p,  5.12229709037114e-08f);
    p = fmaf(x2, p,  1.48572235717979e-05f);
    p = fmaf(x2, p,  6.37261928875436e-04f);
    p = fmaf(x2, p,  4.89352455891786e-03f);
    p = __fmul_rn(xc, p);
    float q = fmaf(x2, 1.19825839466702e-06f, 1.18534705686654e-04f);
    q = fmaf(x2, q, 2.26843463243900e-03f);
    q = fmaf(x2, q, 4.89352518554385e-03f);
    return __fdiv_rn(p, q);
}

__device__ __forceinline__ float gelu_exact(float x) {
    float t = __fdiv_rn(x, 1.4142135623730951f);
    float e = erff(t);
    return __fmul_rn(__fmul_rn(x, __fadd_rn(e, 1.0f)), 0.5f);
}

template<int IN, int OUT>
__device__ __forceinline__ void lin_coef(int o, int& i0, int& i1, float& w0, float& w1) {
    constexpr float INV = (float)((double)IN / (double)OUT);
    float s  = __fadd_rn(__fmul_rn(__fadd_rn((float)o, 0.5f), INV), -0.5f);
    float fl = floorf(s);
    int a0 = (int)fl, a1 = a0 + 1;
    float k0 = __fadd_rn(1.0f, -__fadd_rn(s, -fl));
    float k1 = __fadd_rn(1.0f, -__fadd_rn(__fadd_rn(fl, 1.0f), -s));
    if (a0 < 0)      { k0 = 0.0f; a0 = 0; }
    if (a1 > IN - 1) { k1 = 0.0f; a1 = IN - 1; }
    float S = __fadd_rn(k0, k1);
    i0 = a0; i1 = a1;
    w0 = __fdiv_rn(k0, S);
    w1 = __fdiv_rn(k1, S);
}

__device__ __forceinline__ float fsq_q(float z, int c, float shift8) {
    constexpr float HL8 = (8.0f - 1.0f) * 1.0010000467300415039f / 2.0f;
    constexpr float HL5 = (5.0f - 1.0f) * 1.0010000467300415039f / 2.0f;
    if (c < 3) {
        float b = __fadd_rn(__fmul_rn(xla_tanh(__fadd_rn(z, shift8)), HL8), -0.5f);
        return __fmul_rn(rintf(b), 0.25f);
    } else {
        float b = __fmul_rn(xla_tanh(z), HL5);
        return __fmul_rn(rintf(b), 0.5f);
    }
}

__device__ __forceinline__ float bilerp(const float* __restrict__ base, int stride,
                                        int iy0, int iy1, int ix0, int ix1,
                                        float wy0, float wy1, float wx0, float wx1) {
    float g0 = __fadd_rn(__fmul_rn(wy0, base[iy0 * stride + ix0]),
                         __fmul_rn(wy1, base[iy1 * stride + ix0]));
    float g1 = __fadd_rn(__fmul_rn(wy0, base[iy0 * stride + ix1]),
                         __fmul_rn(wy1, base[iy1 * stride + ix1]));
    return __fadd_rn(__fmul_rn(wx0, g0), __fmul_rn(wx1, g1));
}

// ---------------- stage conv2 weight chunk: dup f32x2 [k6][c12][dy3][4] ----------------
template<int SI, int KB>
__device__ void stage_w2(float* __restrict__ sm, const float* __restrict__ w2g,
                         int tid, int t0) {
    if (tid < t0) return;
    int n = NT - t0;
    for (int i = tid - t0; i < 648; i += n) {
        int k = i / 108, rm = i - k * 108;
        int c = rm / 9, t = rm - c * 9;
        float v = w2g[SI * 2592 + k * 432 + (KB + c) * 9 + t];
        int dst = k * S2K + c * 12 + (t / 3) * 4 + (t % 3);
        *reinterpret_cast<float2*>(sm + OFF_W2P + dst * 2) = make_float2(v, v);
    }
}

// ---------------- stage a: clear tiles (all items) + stage w1/biases ----------------
template<int SI, int H, int W>
__device__ void load_stage(float* __restrict__ sm,
                           const float* __restrict__ w1g, const float* __restrict__ b1g,
                           const float* __restrict__ b2g, int tid) {
    constexpr int P = (H + 2) * (W + 2);
    if constexpr (H == 1) {
        for (int it = 0; it < IT; it++) {
            for (int i = tid; i < 6 * P; i += NT)   sm[OFF_RP + it * RPS + i] = 0.0f;
            for (int i = tid; i < NCH * P; i += NT) sm[OFF_HID + it * HS + i] = 0.0f;
        }
    } else {
        float4 z4 = make_float4(0.f, 0.f, 0.f, 0.f);
        for (int it = 0; it < IT; it++) {
            float4* rp4 = reinterpret_cast<float4*>(sm + OFF_RP + it * RPS);
            float4* hp4 = reinterpret_cast<float4*>(sm + OFF_HID + it * HS);
            for (int i = tid; i < 6 * P / 4; i += NT)   rp4[i] = z4;
            for (int i = tid; i < NCH * P / 4; i += NT) hp4[i] = z4;
        }
    }
    const float4* w1s4 = reinterpret_cast<const float4*>(w1g + SI * 2592);
    float4* d1 = reinterpret_cast<float4*>(sm + OFF_W1);
    for (int i = tid; i < 648; i += NT) d1[i] = w1s4[i];
    if (tid < 48) sm[OFF_B1 + tid] = b1g[SI * 48 + tid];
    if (tid < 6)  sm[OFF_B2 + tid] = b2g[SI * 6 + tid];
}

// ---------------- stage b: resize f -> (H,W), FSQ, emit tokens (all items) ----------------
template<int SI, int H, int W>
__device__ void resize_fsq(float* __restrict__ sm, float* __restrict__ out0,
                           int tid, float shift8) {
    constexpr int HW = H * W;
    constexpr bool LAST = (SI == 7);
    for (int idx = tid; idx < IT * 6 * HW; idx += NT) {
        int item = idx / (6 * HW);
        int rm = idx - item * 6 * HW;
        int c = rm / HW;
        int p = rm - c * HW;
        int y = p / W, x = p - y * W;
        const float* fb = sm + OFF_F + item * FS + c * 256;
        float v;
        if constexpr (H == 16 && W == 16) {
            v = fb[p];
        } else {
            int iy0, iy1, ix0, ix1; float wy0, wy1, wx0, wx1;
            lin_coef<16, H>(y, iy0, iy1, wy0, wy1);
            lin_coef<16, W>(x, ix0, ix1, wx0, wx1);
            v = bilerp(fb, 16, iy0, iy1, ix0, ix1, wy0, wy1, wx0, wx1);
        }
        float t = fsq_q(v, c, shift8);
        out0[item * 3726 + c * HW + p] = t;
        if (!LAST)
            sm[OFF_RP + item * RPS + c * (H + 2) * (W + 2) + (y + 1) * (W + 2) + (x + 1)] = t;
    }
}

// ---------------- conv1 job: one (item, k-pair, full row), chunk of 12 k ----------------
template<int H, int W, int KB>
__device__ __forceinline__ void conv1_job(float* __restrict__ sm, int item, int kp, int y) {
    constexpr int P  = (H + 2) * (W + 2);
    constexpr int W2 = W + 2;
    constexpr int NP = W / 2;
    int k0g = KB + 2 * kp;
    int kl0 = 2 * kp;
    const float* rp = sm + OFF_RP + item * RPS;
    const float* wp = sm + OFF_W1;
    u64 a0[NP], a1[NP];
    {
        u64 b0 = pack2(sm[OFF_B1 + k0g],     sm[OFF_B1 + k0g]);
        u64 b1 = pack2(sm[OFF_B1 + k0g + 1], sm[OFF_B1 + k0g + 1]);
#pragma unroll
        for (int p = 0; p < NP; p++) { a0[p] = b0; a1[p] = b1; }
    }
#pragma unroll 2
    for (int c = 0; c < 6; c++) {
        const float* rb = rp + c * P + y * W2;
        const float* w0 = wp + (k0g * 6 + c) * 9;
        const float* w1 = wp + ((k0g + 1) * 6 + c) * 9;
#pragma unroll
        for (int dy = 0; dy < 3; dy++) {
            const float* rr = rb + dy * W2;
            u64 F[NP + 1];
#pragma unroll
            for (int j = 0; j <= NP; j++) F[j] = lds2(rr + 2 * j);
            float s;
            s = w0[dy * 3 + 0]; u64 t00 = pack2(s, s);
            s = w0[dy * 3 + 1]; u64 t01 = pack2(s, s);
            s = w0[dy * 3 + 2]; u64 t02 = pack2(s, s);
            s = w1[dy * 3 + 0]; u64 t10 = pack2(s, s);
            s = w1[dy * 3 + 1]; u64 t11 = pack2(s, s);
            s = w1[dy * 3 + 2]; u64 t12 = pack2(s, s);
#pragma unroll
            for (int p = 0; p < NP; p++) {
                float alo, ahi, blo, bhi;
                unpack2(F[p], alo, ahi); unpack2(F[p + 1], blo, bhi);
                u64 M = pack2(ahi, blo);
                fma2(a0[p], t00, F[p]); fma2(a0[p], t01, M); fma2(a0[p], t02, F[p + 1]);
                fma2(a1[p], t10, F[p]); fma2(a1[p], t11, M); fma2(a1[p], t12, F[p + 1]);
            }
        }
    }
    float* hp0 = sm + OFF_HID + item * HS + kl0 * P + (y + 1) * W2 + 1;
    float* hp1 = hp0 + P;
#pragma unroll
    for (int p = 0; p < NP; p++) {
        float x0v, x1v;
        unpack2(a0[p], x0v, x1v);
        hp0[2 * p] = gelu_exact(x0v); hp0[2 * p + 1] = gelu_exact(x1v);
        unpack2(a1[p], x0v, x1v);
        hp1[2 * p] = gelu_exact(x0v); hp1[2 * p + 1] = gelu_exact(x1v);
    }
}

// conv1 over all items: IT * 6 k-pairs * H rows jobs (max 288), 1 per thread
template<int H, int W, int KB>
__device__ void conv1(float* __restrict__ sm, int tid) {
    constexpr int NJ1 = 6 * H;
    if (tid >= IT * NJ1) return;
    int item = tid / NJ1, rm = tid - item * NJ1;
    int kp = rm / H, y = rm - kp * H;
    conv1_job<H, W, KB>(sm, item, kp, y);
}

template<int KB>
__device__ void conv1_1(float* __restrict__ sm, int tid) {
    if (tid >= IT * 12) return;
    int item = tid / 12, kl = tid - item * 12;
    int kg = KB + kl;
    const float* rp = sm + OFF_RP + item * RPS;
    const float* w = sm + OFF_W1 + kg * 54;
    float a = sm[OFF_B1 + kg];
#pragma unroll 2
    for (int c = 0; c < 6; c++) {
        const float* rb = rp + c * 9;
#pragma unroll
        for (int t = 0; t < 9; t++)
            a = fmaf(w[c * 9 + t], rb[t], a);
    }
    sm[OFF_HID + item * HS + kl * 9 + 4] = gelu_exact(a);
}

// ---------------- conv2 partial: 12 local channels into persistent regs ----------------
template<int H, int W, int KB>
__device__ void conv2_pass(float* __restrict__ sm, int tid, u64 (&A)[3][2]) {
    constexpr int P  = (H + 2) * (W + 2);
    constexpr int W2 = W + 2;
    constexpr int HW = H * W;
    constexpr int NPAIR = W / 2;
    constexpr int SEGS  = (NPAIR + 1) / 2;
    constexpr int NPLAST = NPAIR - 2 * (SEGS - 1);
    constexpr int NJ1 = 6 * H * SEGS;
    constexpr int NJ  = IT * NJ1;
    constexpr int SMAX = (NJ + NT - 1) / NT;
#pragma unroll
    for (int s = 0; s < SMAX; s++) {
        int j = tid + NT * s;
        if (j >= NJ) break;
        int item = j / NJ1, rm = j - item * NJ1;
        int k = rm / (H * SEGS), rm2 = rm - k * (H * SEGS);
        int y = rm2 / SEGS, seg = rm2 - y * SEGS;
        int x0 = seg * 4;
        u64& acc0 = A[s][0];
        u64& acc1 = A[s][1];
        if constexpr (KB == 0) {
            u64 b = pack2(sm[OFF_B2 + k], sm[OFF_B2 + k]);
            acc0 = b; acc1 = b;
        }
        const float* hp = sm + OFF_HID + item * HS;
        const float* wp = sm + OFF_W2P;
#pragma unroll 2
        for (int c = 0; c < NCH; c++) {
            const float* rb = hp + c * P + y * W2 + x0;
            const float* w  = wp + (k * S2K + c * 12) * 2;
#pragma unroll
            for (int dy = 0; dy < 3; dy++) {
                const float* rr = rb + dy * W2;
                u64 F0 = lds2(rr), F1 = lds2(rr + 2), F2 = lds2(rr + 4);
                u64 t0 = lds2(w + (dy * 4 + 0) * 2);
                u64 t1 = lds2(w + (dy * 4 + 1) * 2);
                u64 t2 = lds2(w + (dy * 4 + 2) * 2);
                float l0, h0, l1, h1, l2, h2;
                unpack2(F0, l0, h0); unpack2(F1, l1, h1); unpack2(F2, l2, h2);
                u64 M0 = pack2(h0, l1), M1 = pack2(h1, l2);
                fma2(acc0, t0, F0); fma2(acc0, t1, M0); fma2(acc0, t2, F1);
                fma2(acc1, t0, F1); fma2(acc1, t1, M1); fma2(acc1, t2, F2);
            }
        }
        if constexpr (KB == 36) {
            bool last1 = (NPLAST == 1) && (seg == SEGS - 1);
            float* zb = sm + OFF_RP + item * RPS + k * HW + y * W + x0;  // zbuf alias
            *reinterpret_cast<u64*>(zb) = acc0;
            if (!last1) *reinterpret_cast<u64*>(zb + 2) = acc1;
        }
    }
}

template<int KB>
__device__ void conv2_1_pass(float* __restrict__ sm, int tid, float& acc) {
    if (tid >= IT * 6) return;
    int item = tid / 6, k = tid - item * 6;
    if constexpr (KB == 0) acc = sm[OFF_B2 + k];
    const float* hp = sm + OFF_HID + item * HS;
    const float* wp = sm + OFF_W2P;
#pragma unroll 2
    for (int c = 0; c < NCH; c++) {
        const float* rb = hp + c * 9;
        const float* w  = wp + (k * S2K + c * 12) * 2;
#pragma unroll
        for (int dy = 0; dy < 3; dy++)
#pragma unroll
            for (int dx = 0; dx < 3; dx++)
                acc = fmaf(w[(dy * 4 + dx) * 2], rb[dy * 3 + dx], acc);
    }
    if constexpr (KB == 36) sm[OFF_RP + item * RPS + k] = acc;
}

// ---------------- stage e: upsample z (H,W)->(16,16), f -= z (all items) ----------------
template<int H, int W>
__device__ void upsub(float* __restrict__ sm, int tid) {
    constexpr int HW = H * W;
    for (int idx = tid; idx < IT * 1536; idx += NT) {
        int item = idx / 1536, r = idx - item * 1536;
        int c = r >> 8;
        int p = r & 255;
        int Y = p >> 4, X = p & 15;
        int iy0, iy1, ix0, ix1; float wy0, wy1, wx0, wx1;
        lin_coef<H, 16>(Y, iy0, iy1, wy0, wy1);
        lin_coef<W, 16>(X, ix0, ix1, wx0, wx1);
        float v = bilerp(sm + OFF_RP + item * RPS + c * HW, W,
                         iy0, iy1, ix0, ix1, wy0, wy1, wx0, wx1);
        sm[OFF_F + item * FS + r] = __fadd_rn(sm[OFF_F + item * FS + r], -v);
    }
}

// ---------------- one scale ----------------
template<int SI, int H, int W>
__device__ void do_scale(float* __restrict__ sm,
                         const float* __restrict__ w1g, const float* __restrict__ b1g,
                         const float* __restrict__ w2g, const float* __restrict__ b2g,
                         float* __restrict__ out0, int tid, float shift8,
                         u64 (&A)[3][2], float& accS) {
    constexpr bool LAST = (SI == 7);
    if constexpr (!LAST) {
        load_stage<SI, H, W>(sm, w1g, b1g, b2g, tid);
        stage_w2<SI, 0>(sm, w2g, tid, 0);
        __syncthreads();
    }
    resize_fsq<SI, H, W>(sm, out0, tid, shift8);
    if constexpr (LAST) return;
    __syncthreads();
    if constexpr (H == 1) {
        conv1_1<0>(sm, tid);                                        __syncthreads();
        conv2_1_pass<0>(sm, tid, accS);                             __syncthreads();
        conv1_1<12>(sm, tid); stage_w2<SI, 12>(sm, w2g, tid, 48);   __syncthreads();
        conv2_1_pass<12>(sm, tid, accS);                            __syncthreads();
        conv1_1<24>(sm, tid); stage_w2<SI, 24>(sm, w2g, tid, 48);   __syncthreads();
        conv2_1_pass<24>(sm, tid, accS);                            __syncthreads();
        conv1_1<36>(sm, tid); stage_w2<SI, 36>(sm, w2g, tid, 48);   __syncthreads();
        conv2_1_pass<36>(sm, tid, accS);                            __syncthreads();
    } else {
        constexpr int T0 = IT * 6 * H;   // conv1 busy threads (<= 288)
        conv1<H, W, 0>(sm, tid);                                     __syncthreads();
        conv2_pass<H, W, 0>(sm, tid, A);                             __syncthreads();
        conv1<H, W, 12>(sm, tid); stage_w2<SI, 12>(sm, w2g, tid, T0); __syncthreads();
        conv2_pass<H, W, 12>(sm, tid, A);                            __syncthreads();
        conv1<H, W, 24>(sm, tid); stage_w2<SI, 24>(sm, w2g, tid, T0); __syncthreads();
        conv2_pass<H, W, 24>(sm, tid, A);                            __syncthreads();
        conv1<H, W, 36>(sm, tid); stage_w2<SI, 36>(sm, w2g, tid, T0); __syncthreads();
        conv2_pass<H, W, 36>(sm, tid, A);                            __syncthreads();
    }
    upsub<H, W>(sm, tid);
    __syncthreads();
}

__global__ void __launch_bounds__(NT, 2)
var_tokenizer_kernel(const float* __restrict__ lat,
                     const float* __restrict__ w1, const float* __restrict__ b1,
                     const float* __restrict__ w2, const float* __restrict__ b2,
                     float* __restrict__ out) {
    extern __shared__ float sm[];
    int blk = blockIdx.x;
    int tid = threadIdx.x;

    // load f for all 4 items (contiguous 4*1536 floats = 1536 float4)
    const float4* src  = reinterpret_cast<const float4*>(lat + (size_t)(IT * blk) * 1536);
    float4*       dstf = reinterpret_cast<float4*>(sm + OFF_F);
    for (int i = tid; i < 1536; i += NT) dstf[i] = src[i];

    constexpr float HL8 = (8.0f - 1.0f) * 1.0010000467300415039f / 2.0f;
    float ratio = __fdiv_rn(0.5f, HL8);
    float shift8 = (float)atanh((double)ratio);

    float* outb = out + (size_t)(IT * blk) * 3726;
    u64 A[3][2];
    float accS = 0.0f;
    __syncthreads();

    do_scale<0, 1, 1>  (sm, w1, b1, w2, b2, outb + 0,    tid, shift8, A, accS);
    do_scale<1, 2, 2>  (sm, w1, b1, w2, b2, outb + 6,    tid, shift8, A, accS);
    do_scale<2, 4, 4>  (sm, w1, b1, w2, b2, outb + 30,   tid, shift8, A, accS);
    do_scale<3, 6, 6>  (sm, w1, b1, w2, b2, outb + 126,  tid, shift8, A, accS);
    do_scale<4, 8, 8>  (sm, w1, b1, w2, b2, outb + 342,  tid, shift8, A, accS);
    do_scale<5, 10, 10>(sm, w1, b1, w2, b2, outb + 726,  tid, shift8, A, accS);
    do_scale<6, 12, 12>(sm, w1, b1, w2, b2, outb + 1326, tid, shift8, A, accS);
    do_scale<7, 16, 16>(sm, w1, b1, w2, b2, outb + 2190, tid, shift8, A, accS);
}

extern "C" void kernel_launch(void* const* d_in, const int* in_sizes, int n_in,
                              void* d_out, int out_size) {
    const float* lat = (const float*)d_in[0];
    const float* w1  = (const float*)d_in[1];
    const float* b1  = (const float*)d_in[2];
    const float* w2  = (const float*)d_in[3];
    const float* b2  = (const float*)d_in[4];
    float* out = (float*)d_out;

    int B = in_sizes[0] / 1536;

    cudaFuncSetAttribute(var_tokenizer_kernel,
                         cudaFuncAttributeMaxDynamicSharedMemorySize, SMEM_BYTES);
    var_tokenizer_kernel<<<B / IT, NT, SMEM_BYTES>>>(lat, w1, b1, w2, b2, out);
}

// round 17
// speedup vs baseline: 1.1939x; 1.1939x over previous
#include <cuda_runtime.h>
#include <math.h>

#define NT 256
typedef unsigned long long u64;

// ---------------- shared memory layout (floats), 2 items per CTA ----------------
constexpr int FS  = 1536;  // f per-item stride
constexpr int RPS = 1176;  // rp per-item stride (max 6*196)
constexpr int NCH = 16;    // hid channels per chunk (3 chunks of 16)
constexpr int HS  = NCH * 196;  // hid per-item stride = 3136
constexpr int ZBS = 864;   // zbuf per-item stride (6 * max HW=144)
constexpr int OFF_F    = 0;      // f:    [2][1536] = 3072
constexpr int OFF_RP   = 3072;   // rp:   [2][1176] = 2352
constexpr int OFF_HID  = 5424;   // hid:  [2][16*196] = 6272
constexpr int OFF_W1   = 11696;  // conv1 weights plain [48][6][9] = 2592 (shared)
constexpr int OFF_W2P  = 14288;  // conv2 dup f32x2 chunk [6][193] = 2316 (shared)
constexpr int OFF_ZB   = 16604;  // zbuf: [2][864] = 1728 (separate from rp!)
constexpr int OFF_B1   = 18332;  // 48
constexpr int OFF_B2   = 18380;  // 8
constexpr int SMEM_FLOATS = 18388;
constexpr int SMEM_BYTES  = SMEM_FLOATS * 4;   // 73,552 B -> 3 blocks/SM (220.7KB)

constexpr int S2K = 193;   // conv2 per-k stride in f32x2 (16*12 + 1 pad)

// ---------------- f32x2 packed helpers ----------------
__device__ __forceinline__ u64 pack2(float lo, float hi) {
    u64 r; asm("mov.b64 %0, {%1, %2};" : "=l"(r) : "f"(lo), "f"(hi)); return r;
}
__device__ __forceinline__ void unpack2(u64 v, float& lo, float& hi) {
    asm("mov.b64 {%0, %1}, %2;" : "=f"(lo), "=f"(hi) : "l"(v));
}
__device__ __forceinline__ void fma2(u64& d, u64 a, u64 b) {
    asm("fma.rn.f32x2 %0, %1, %2, %0;" : "+l"(d) : "l"(a), "l"(b));
}
__device__ __forceinline__ u64 lds2(const float* p) {
    return *reinterpret_cast<const u64*>(p);
}

// ---------------- XLA-exact tanh (verified bit-exact) ----------------
__device__ __forceinline__ float xla_tanh(float x) {
    if (fabsf(x) < 0.0004f) return x;
    float xc = fminf(fmaxf(x, -7.90531110763549805f), 7.90531110763549805f);
    float x2 = __fmul_rn(xc, xc);
    float p = fmaf(x2, -2.76076847742355e-16f, 2.00018790482477e-13f);
    p = fmaf(x2, p, -8.60467152213735e-11f);
    p = fmaf(x2, p,  5.12229709037114e-08f);
    p = fmaf(x2, p,  1.48572235717979e-05f);
    p = fmaf(x2, p,  6.37261928875436e-04f);
    p = fmaf(x2, p,  4.89352455891786e-03f);
    p = __fmul_rn(xc, p);
    float q = fmaf(x2, 1.19825839466702e-06f, 1.18534705686654e-04f);
    q = fmaf(x2, q, 2.26843463243900e-03f);
    q = fmaf(x2, q, 4.89352518554385e-03f);
    return __fdiv_rn(p, q);
}

__device__ __forceinline__ float gelu_exact(float x) {
    float t = __fdiv_rn(x, 1.4142135623730951f);
    float e = erff(t);
    return __fmul_rn(__fmul_rn(x, __fadd_rn(e, 1.0f)), 0.5f);
}

template<int IN, int OUT>
__device__ __forceinline__ void lin_coef(int o, int& i0, int& i1, float& w0, float& w1) {
    constexpr float INV = (float)((double)IN / (double)OUT);
    float s  = __fadd_rn(__fmul_rn(__fadd_rn((float)o, 0.5f), INV), -0.5f);
    float fl = floorf(s);
    int a0 = (int)fl, a1 = a0 + 1;
    float k0 = __fadd_rn(1.0f, -__fadd_rn(s, -fl));
    float k1 = __fadd_rn(1.0f, -__fadd_rn(__fadd_rn(fl, 1.0f), -s));
    if (a0 < 0)      { k0 = 0.0f; a0 = 0; }
    if (a1 > IN - 1) { k1 = 0.0f; a1 = IN - 1; }
    float S = __fadd_rn(k0, k1);
    i0 = a0; i1 = a1;
    w0 = __fdiv_rn(k0, S);
    w1 = __fdiv_rn(k1, S);
}

__device__ __forceinline__ float fsq_q(float z, int c, float shift8) {
    constexpr float HL8 = (8.0f - 1.0f) * 1.0010000467300415039f / 2.0f;
    constexpr float HL5 = (5.0f - 1.0f) * 1.0010000467300415039f / 2.0f;
    if (c < 3) {
        float b = __fadd_rn(__fmul_rn(xla_tanh(__fadd_rn(z, shift8)), HL8), -0.5f);
        return __fmul_rn(rintf(b), 0.25f);
    } else {
        float b = __fmul_rn(xla_tanh(z), HL5);
        return __fmul_rn(rintf(b), 0.5f);
    }
}

__device__ __forceinline__ float bilerp(const float* __restrict__ base, int stride,
                                        int iy0, int iy1, int ix0, int ix1,
                                        float wy0, float wy1, float wx0, float wx1) {
    float g0 = __fadd_rn(__fmul_rn(wy0, base[iy0 * stride + ix0]),
                         __fmul_rn(wy1, base[iy1 * stride + ix0]));
    float g1 = __fadd_rn(__fmul_rn(wy0, base[iy0 * stride + ix1]),
                         __fmul_rn(wy1, base[iy1 * stride + ix1]));
    return __fadd_rn(__fmul_rn(wx0, g0), __fmul_rn(wx1, g1));
}

// ---------------- stage conv2 weight chunk: dup f32x2 [k6][c16][dy3][4] ----------------
template<int SI, int KB>
__device__ void stage_w2(float* __restrict__ sm, const float* __restrict__ w2g,
                         int tid, int t0) {
    if (tid < t0) return;
    int n = NT - t0;
    for (int i = tid - t0; i < 864; i += n) {
        int k = i / 144, rm = i - k * 144;
        int c = rm / 9, t = rm - c * 9;
        float v = w2g[SI * 2592 + k * 432 + (KB + c) * 9 + t];
        int dst = k * S2K + c * 12 + (t / 3) * 4 + (t % 3);
        *reinterpret_cast<float2*>(sm + OFF_W2P + dst * 2) = make_float2(v, v);
    }
}

// ---------------- clear tiles (both items) + stage w1/biases for scale SI ----------------
template<int SI, int H, int W>
__device__ void load_stage(float* __restrict__ sm,
                           const float* __restrict__ w1g, const float* __restrict__ b1g,
                           const float* __restrict__ b2g, int tid) {
    constexpr int P = (H + 2) * (W + 2);
    if constexpr (H == 1) {
        for (int it = 0; it < 2; it++) {
            for (int i = tid; i < 6 * P; i += NT)   sm[OFF_RP + it * RPS + i] = 0.0f;
            for (int i = tid; i < NCH * P; i += NT) sm[OFF_HID + it * HS + i] = 0.0f;
        }
    } else {
        float4 z4 = make_float4(0.f, 0.f, 0.f, 0.f);
        for (int it = 0; it < 2; it++) {
            float4* rp4 = reinterpret_cast<float4*>(sm + OFF_RP + it * RPS);
            float4* hp4 = reinterpret_cast<float4*>(sm + OFF_HID + it * HS);
            for (int i = tid; i < 6 * P / 4; i += NT)   rp4[i] = z4;
            for (int i = tid; i < NCH * P / 4; i += NT) hp4[i] = z4;
        }
    }
    const float4* w1s4 = reinterpret_cast<const float4*>(w1g + SI * 2592);
    float4* d1 = reinterpret_cast<float4*>(sm + OFF_W1);
    for (int i = tid; i < 648; i += NT) d1[i] = w1s4[i];
    if (tid < 48) sm[OFF_B1 + tid] = b1g[SI * 48 + tid];
    if (tid < 6)  sm[OFF_B2 + tid] = b2g[SI * 6 + tid];
}

// ---------------- resize f -> (H,W), FSQ, emit tokens (both items) ----------------
template<int SI, int H, int W>
__device__ void resize_fsq(float* __restrict__ sm, float* __restrict__ out0,
                           int tid, float shift8) {
    constexpr int HW = H * W;
    constexpr bool LAST = (SI == 7);
    for (int idx = tid; idx < 2 * 6 * HW; idx += NT) {
        int item = idx / (6 * HW);
        int rm = idx - item * 6 * HW;
        int c = rm / HW;
        int p = rm - c * HW;
        int y = p / W, x = p - y * W;
        const float* fb = sm + OFF_F + item * FS + c * 256;
        float v;
        if constexpr (H == 16 && W == 16) {
            v = fb[p];
        } else {
            int iy0, iy1, ix0, ix1; float wy0, wy1, wx0, wx1;
            lin_coef<16, H>(y, iy0, iy1, wy0, wy1);
            lin_coef<16, W>(x, ix0, ix1, wx0, wx1);
            v = bilerp(fb, 16, iy0, iy1, ix0, ix1, wy0, wy1, wx0, wx1);
        }
        float t = fsq_q(v, c, shift8);
        out0[item * 3726 + c * HW + p] = t;
        if (!LAST)
            sm[OFF_RP + item * RPS + c * (H + 2) * (W + 2) + (y + 1) * (W + 2) + (x + 1)] = t;
    }
}

// ---------------- conv1 job: one (item, k-pair, full row) ----------------
template<int H, int W, int KB>
__device__ __forceinline__ void conv1_job(float* __restrict__ sm, int item, int kp, int y) {
    constexpr int P  = (H + 2) * (W + 2);
    constexpr int W2 = W + 2;
    constexpr int NP = W / 2;
    int k0g = KB + 2 * kp;
    int kl0 = 2 * kp;
    const float* rp = sm + OFF_RP + item * RPS;
    const float* wp = sm + OFF_W1;
    u64 a0[NP], a1[NP];
    {
        u64 b0 = pack2(sm[OFF_B1 + k0g],     sm[OFF_B1 + k0g]);
        u64 b1 = pack2(sm[OFF_B1 + k0g + 1], sm[OFF_B1 + k0g + 1]);
#pragma unroll
        for (int p = 0; p < NP; p++) { a0[p] = b0; a1[p] = b1; }
    }
#pragma unroll 2
    for (int c = 0; c < 6; c++) {
        const float* rb = rp + c * P + y * W2;
        const float* w0 = wp + (k0g * 6 + c) * 9;
        const float* w1 = wp + ((k0g + 1) * 6 + c) * 9;
#pragma unroll
        for (int dy = 0; dy < 3; dy++) {
            const float* rr = rb + dy * W2;
            u64 F[NP + 1];
#pragma unroll
            for (int j = 0; j <= NP; j++) F[j] = lds2(rr + 2 * j);
            float s;
            s = w0[dy * 3 + 0]; u64 t00 = pack2(s, s);
            s = w0[dy * 3 + 1]; u64 t01 = pack2(s, s);
            s = w0[dy * 3 + 2]; u64 t02 = pack2(s, s);
            s = w1[dy * 3 + 0]; u64 t10 = pack2(s, s);
            s = w1[dy * 3 + 1]; u64 t11 = pack2(s, s);
            s = w1[dy * 3 + 2]; u64 t12 = pack2(s, s);
#pragma unroll
            for (int p = 0; p < NP; p++) {
                float alo, ahi, blo, bhi;
                unpack2(F[p], alo, ahi); unpack2(F[p + 1], blo, bhi);
                u64 M = pack2(ahi, blo);
                fma2(a0[p], t00, F[p]); fma2(a0[p], t01, M); fma2(a0[p], t02, F[p + 1]);
                fma2(a1[p], t10, F[p]); fma2(a1[p], t11, M); fma2(a1[p], t12, F[p + 1]);
            }
        }
    }
    float* hp0 = sm + OFF_HID + item * HS + kl0 * P + (y + 1) * W2 + 1;
    float* hp1 = hp0 + P;
#pragma unroll
    for (int p = 0; p < NP; p++) {
        float x0v, x1v;
        unpack2(a0[p], x0v, x1v);
        hp0[2 * p] = gelu_exact(x0v); hp0[2 * p + 1] = gelu_exact(x1v);
        unpack2(a1[p], x0v, x1v);
        hp1[2 * p] = gelu_exact(x0v); hp1[2 * p + 1] = gelu_exact(x1v);
    }
}

// conv1 over both items: 2 * 8 k-pairs * H rows jobs, 1 per thread
template<int H, int W, int KB>
__device__ void conv1(float* __restrict__ sm, int tid) {
    constexpr int NJ1 = 8 * H;
    if (tid >= 2 * NJ1) return;
    int item = tid / NJ1, rm = tid - item * NJ1;
    int kp = rm / H, y = rm - kp * H;
    conv1_job<H, W, KB>(sm, item, kp, y);
}

template<int KB>
__device__ void conv1_1(float* __restrict__ sm, int tid) {
    if (tid >= 32) return;
    int item = tid / 16, kl = tid - item * 16;
    int kg = KB + kl;
    const float* rp = sm + OFF_RP + item * RPS;
    const float* w = sm + OFF_W1 + kg * 54;
    float a = sm[OFF_B1 + kg];
#pragma unroll 2
    for (int c = 0; c < 6; c++) {
        const float* rb = rp + c * 9;
#pragma unroll
        for (int t = 0; t < 9; t++)
            a = fmaf(w[c * 9 + t], rb[t], a);
    }
    sm[OFF_HID + item * HS + kl * 9 + 4] = gelu_exact(a);
}

// ---------------- conv2 partial: 16 local channels into persistent regs ----------------
template<int H, int W, int KB>
__device__ void conv2_pass(float* __restrict__ sm, int tid, u64 (&A)[2][2]) {
    constexpr int P  = (H + 2) * (W + 2);
    constexpr int W2 = W + 2;
    constexpr int HW = H * W;
    constexpr int NPAIR = W / 2;
    constexpr int SEGS  = (NPAIR + 1) / 2;
    constexpr int NPLAST = NPAIR - 2 * (SEGS - 1);
    constexpr int NJ1 = 6 * H * SEGS;
    constexpr int NJ  = 2 * NJ1;
    constexpr int SMAX = (NJ + NT - 1) / NT;
#pragma unroll
    for (int s = 0; s < SMAX; s++) {
        int j = tid + NT * s;
        if (j >= NJ) break;
        int item = j / NJ1, rm = j - item * NJ1;
        int k = rm / (H * SEGS), rm2 = rm - k * (H * SEGS);
        int y = rm2 / SEGS, seg = rm2 - y * SEGS;
        int x0 = seg * 4;
        u64& acc0 = A[s][0];
        u64& acc1 = A[s][1];
        if constexpr (KB == 0) {
            u64 b = pack2(sm[OFF_B2 + k], sm[OFF_B2 + k]);
            acc0 = b; acc1 = b;
        }
        const float* hp = sm + OFF_HID + item * HS;
        const float* wp = sm + OFF_W2P;
#pragma unroll 2
        for (int c = 0; c < NCH; c++) {
            const float* rb = hp + c * P + y * W2 + x0;
            const float* w  = wp + (k * S2K + c * 12) * 2;
#pragma unroll
            for (int dy = 0; dy < 3; dy++) {
                const float* rr = rb + dy * W2;
                u64 F0 = lds2(rr), F1 = lds2(rr + 2), F2 = lds2(rr + 4);
                u64 t0 = lds2(w + (dy * 4 + 0) * 2);
                u64 t1 = lds2(w + (dy * 4 + 1) * 2);
                u64 t2 = lds2(w + (dy * 4 + 2) * 2);
                float l0, h0, l1, h1, l2, h2;
                unpack2(F0, l0, h0); unpack2(F1, l1, h1); unpack2(F2, l2, h2);
                u64 M0 = pack2(h0, l1), M1 = pack2(h1, l2);
                fma2(acc0, t0, F0); fma2(acc0, t1, M0); fma2(acc0, t2, F1);
                fma2(acc1, t0, F1); fma2(acc1, t1, M1); fma2(acc1, t2, F2);
            }
        }
        if constexpr (KB == 32) {
            bool last1 = (NPLAST == 1) && (seg == SEGS - 1);
            float* zb = sm + OFF_ZB + item * ZBS + k * HW + y * W + x0;
            *reinterpret_cast<u64*>(zb) = acc0;
            if (!last1) *reinterpret_cast<u64*>(zb + 2) = acc1;
        }
    }
}

template<int KB>
__device__ void conv2_1_pass(float* __restrict__ sm, int tid, float& acc) {
    if (tid >= 12) return;
    int item = tid / 6, k = tid - item * 6;
    if constexpr (KB == 0) acc = sm[OFF_B2 + k];
    const float* hp = sm + OFF_HID + item * HS;
    const float* wp = sm + OFF_W2P;
#pragma unroll 2
    for (int c = 0; c < NCH; c++) {
        const float* rb = hp + c * 9;
        const float* w  = wp + (k * S2K + c * 12) * 2;
#pragma unroll
        for (int dy = 0; dy < 3; dy++)
#pragma unroll
            for (int dx = 0; dx < 3; dx++)
                acc = fmaf(w[(dy * 4 + dx) * 2], rb[dy * 3 + dx], acc);
    }
    if constexpr (KB == 32) sm[OFF_ZB + item * ZBS + k] = acc;
}

// ---------------- upsample z (H,W)->(16,16), f -= z (both items) ----------------
template<int H, int W>
__device__ void upsub(float* __restrict__ sm, int tid) {
    constexpr int HW = H * W;
    for (int idx = tid; idx < 2 * 1536; idx += NT) {
        int item = idx / 1536, r = idx - item * 1536;
        int c = r >> 8;
        int p = r & 255;
        int Y = p >> 4, X = p & 15;
        int iy0, iy1, ix0, ix1; float wy0, wy1, wx0, wx1;
        lin_coef<H, 16>(Y, iy0, iy1, wy0, wy1);
        lin_coef<W, 16>(X, ix0, ix1, wx0, wx1);
        float v = bilerp(sm + OFF_ZB + item * ZBS + c * HW, W,
                         iy0, iy1, ix0, ix1, wy0, wy1, wx0, wx1);
        sm[OFF_F + item * FS + r] = __fadd_rn(sm[OFF_F + item * FS + r], -v);
    }
}

// ---------------- one scale (assumes its tiles/weights were staged by the
// previous scale's merged epilogue; stages the NEXT scale's in its own) ----------------
template<int SI, int H, int W, int NH, int NW>
__device__ void do_scale(float* __restrict__ sm,
                         const float* __restrict__ w1g, const float* __restrict__ b1g,
                         const float* __restrict__ w2g, const float* __restrict__ b2g,
                         float* __restrict__ out0, int tid, float shift8,
                         u64 (&A)[2][2], float& accS) {
    constexpr bool LAST = (SI == 7);
    resize_fsq<SI, H, W>(sm, out0, tid, shift8);
    if constexpr (LAST) return;
    __syncthreads();
    if constexpr (H == 1) {
        conv1_1<0>(sm, tid);                                       __syncthreads();
        conv2_1_pass<0>(sm, tid, accS);                            __syncthreads();
        conv1_1<16>(sm, tid); stage_w2<SI, 16>(sm, w2g, tid, 32);  __syncthreads();
        conv2_1_pass<16>(sm, tid, accS);                           __syncthreads();
        conv1_1<32>(sm, tid); stage_w2<SI, 32>(sm, w2g, tid, 32);  __syncthreads();
        conv2_1_pass<32>(sm, tid, accS);                           __syncthreads();
    } else {
        constexpr int T0 = 16 * H;   // conv1 busy threads
        conv1<H, W, 0>(sm, tid);                                      __syncthreads();
        conv2_pass<H, W, 0>(sm, tid, A);                              __syncthreads();
        conv1<H, W, 16>(sm, tid); stage_w2<SI, 16>(sm, w2g, tid, T0); __syncthreads();
        conv2_pass<H, W, 16>(sm, tid, A);                             __syncthreads();
        conv1<H, W, 32>(sm, tid); stage_w2<SI, 32>(sm, w2g, tid, T0); __syncthreads();
        conv2_pass<H, W, 32>(sm, tid, A);                             __syncthreads();
    }
    // merged epilogue: upsub (zbuf->f) runs concurrently with staging the next
    // scale's tiles/weights (disjoint smem regions; zbuf is no longer aliased to rp)
    upsub<H, W>(sm, tid);
    if constexpr (SI < 6) {
        load_stage<SI + 1, NH, NW>(sm, w1g, b1g, b2g, tid);
        stage_w2<SI + 1, 0>(sm, w2g, tid, 0);
    }
    __syncthreads();
}

__global__ void __launch_bounds__(NT, 3)
var_tokenizer_kernel(const float* __restrict__ lat,
                     const float* __restrict__ w1, const float* __restrict__ b1,
                     const float* __restrict__ w2, const float* __restrict__ b2,
                     float* __restrict__ out) {
    extern __shared__ float sm[];
    int blk = blockIdx.x;
    int tid = threadIdx.x;

    // prologue: load f for both items, stage scale-0 tiles + weights, one sync
    const float4* src  = reinterpret_cast<const float4*>(lat + (size_t)(2 * blk) * 1536);
    float4*       dstf = reinterpret_cast<float4*>(sm + OFF_F);
    for (int i = tid; i < 768; i += NT) dstf[i] = src[i];
    load_stage<0, 1, 1>(sm, w1, b1, b2, tid);
    stage_w2<0, 0>(sm, w2, tid, 0);

    constexpr float HL8 = (8.0f - 1.0f) * 1.0010000467300415039f / 2.0f;
    float ratio = __fdiv_rn(0.5f, HL8);
    float shift8 = (float)atanh((double)ratio);

    float* outb = out + (size_t)(2 * blk) * 3726;
    u64 A[2][2];
    float accS = 0.0f;
    __syncthreads();

    do_scale<0, 1, 1, 2, 2>    (sm, w1, b1, w2, b2, outb + 0,    tid, shift8, A, accS);
    do_scale<1, 2, 2, 4, 4>    (sm, w1, b1, w2, b2, outb + 6,    tid, shift8, A, accS);
    do_scale<2, 4, 4, 6, 6>    (sm, w1, b1, w2, b2, outb + 30,   tid, shift8, A, accS);
    do_scale<3, 6, 6, 8, 8>    (sm, w1, b1, w2, b2, outb + 126,  tid, shift8, A, accS);
    do_scale<4, 8, 8, 10, 10>  (sm, w1, b1, w2, b2, outb + 342,  tid, shift8, A, accS);
    do_scale<5, 10, 10, 12, 12>(sm, w1, b1, w2, b2, outb + 726,  tid, shift8, A, accS);
    do_scale<6, 12, 12, 16, 16>(sm, w1, b1, w2, b2, outb + 1326, tid, shift8, A, accS);
    do_scale<7, 16, 16, 16, 16>(sm, w1, b1, w2, b2, outb + 2190, tid, shift8, A, accS);
}

extern "C" void kernel_launch(void* const* d_in, const int* in_sizes, int n_in,
                              void* d_out, int out_size) {
    const float* lat = (const float*)d_in[0];
    const float* w1  = (const float*)d_in[1];
    const float* b1  = (const float*)d_in[2];
    const float* w2  = (const float*)d_in[3];
    const float* b2  = (const float*)d_in[4];
    float* out = (float*)d_out;

    int B = in_sizes[0] / 1536;

    cudaFuncSetAttribute(var_tokenizer_kernel,
                         cudaFuncAttributeMaxDynamicSharedMemorySize, SMEM_BYTES);
    var_tokenizer_kernel<<<B / 2, NT, SMEM_BYTES>>>(lat, w1, b1, w2, b2, out);
}